// round 7
// baseline (speedup 1.0000x reference)
#include <cuda_runtime.h>
#include <cuda_fp16.h>
#include <math.h>
#include <stdint.h>

// Shapes: B=2, S=128, H=8, KD=64, D=512, FB=512
#define NB   2
#define NS   128
#define NH   8
#define NKD  64
#define ND   512
#define NFB  512
#define NBHQ 2048

// ---------------- device scratch ----------------
__device__ float g_eqk[NB*NS*ND];
__device__ float g_eqv[NB*NS*ND];
__device__ float g_ekk[NB*NS*ND];
__device__ float g_evv[NB*NS*ND];
__device__ float g_logits[NBHQ*NS];
__device__ float g_pool[NBHQ*NFB];
__device__ float g_O[NB*NS*ND];

__device__ __forceinline__ float elu_f(float x) {
    return (x > 0.f) ? x : expm1f(x);
}

__device__ __forceinline__ uint32_t smem_to_u32(const void* smem_ptr) {
    uint32_t addr;
    asm("{ .reg .u64 tmp; cvta.to.shared.u64 tmp, %1; cvt.u32.u64 %0, tmp; }"
        : "=r"(addr) : "l"(smem_ptr));
    return addr;
}

#define LDSM4(r0, r1, r2, r3, addr) \
    asm volatile("ldmatrix.sync.aligned.m8n8.x4.shared.b16 {%0,%1,%2,%3}, [%4];" \
        : "=r"(r0), "=r"(r1), "=r"(r2), "=r"(r3) : "r"(addr))

#define MMA16816(c, a0, a1, a2, a3, b0, b1) \
    asm volatile("mma.sync.aligned.m16n8k16.row.col.f32.f16.f16.f32 " \
        "{%0,%1,%2,%3}, {%4,%5,%6,%7}, {%8,%9}, {%0,%1,%2,%3};" \
        : "+f"((c)[0]), "+f"((c)[1]), "+f"((c)[2]), "+f"((c)[3]) \
        : "r"(a0), "r"(a1), "r"(a2), "r"(a3), "r"(b0), "r"(b1))

// =====================================================================
// Kernel 1: four projections + elu
// =====================================================================
__global__ __launch_bounds__(256) void k_proj(
    const float* __restrict__ q, const float* __restrict__ v,
    const float* __restrict__ Wkq, const float* __restrict__ bkq,
    const float* __restrict__ Wvq, const float* __restrict__ bvq,
    const float* __restrict__ Wk,  const float* __restrict__ bk,
    const float* __restrict__ Wv,  const float* __restrict__ bv)
{
    int z = blockIdx.z;
    const float* X    = (z < 2) ? q : v;
    const float* W    = (z == 0) ? Wkq : (z == 1) ? Wvq : (z == 2) ? Wk : Wv;
    const float* bias = (z == 0) ? bkq : (z == 1) ? bvq : (z == 2) ? bk : bv;
    float* Y          = (z == 0) ? g_eqk : (z == 1) ? g_eqv : (z == 2) ? g_ekk : g_evv;

    __shared__ float As[16][64];
    __shared__ float Bs[16][64];

    int tid = threadIdx.x;
    int tx = tid & 15;
    int ty = tid >> 4;
    int n0 = blockIdx.x * 64;
    int m0 = blockIdx.y * 64;

    float acc[4][4];
    #pragma unroll
    for (int i = 0; i < 4; i++)
        #pragma unroll
        for (int j = 0; j < 4; j++) acc[i][j] = 0.f;

    int ar = tid >> 2;
    int ak = (tid & 3) << 2;
    int br = tid >> 4;
    int bc = (tid & 15) << 2;

    for (int k0 = 0; k0 < ND; k0 += 16) {
        float4 av = *(const float4*)(X + (m0 + ar) * ND + k0 + ak);
        float4 bvv = *(const float4*)(W + (k0 + br) * ND + n0 + bc);
        __syncthreads();
        As[ak + 0][ar] = av.x;
        As[ak + 1][ar] = av.y;
        As[ak + 2][ar] = av.z;
        As[ak + 3][ar] = av.w;
        *(float4*)(&Bs[br][bc]) = bvv;
        __syncthreads();
        #pragma unroll
        for (int kk = 0; kk < 16; kk++) {
            float a[4], bb_[4];
            #pragma unroll
            for (int i = 0; i < 4; i++) a[i] = As[kk][ty * 4 + i];
            #pragma unroll
            for (int j = 0; j < 4; j++) bb_[j] = Bs[kk][tx * 4 + j];
            #pragma unroll
            for (int i = 0; i < 4; i++)
                #pragma unroll
                for (int j = 0; j < 4; j++)
                    acc[i][j] = fmaf(a[i], bb_[j], acc[i][j]);
        }
    }

    #pragma unroll
    for (int i = 0; i < 4; i++) {
        int row = m0 + ty * 4 + i;
        #pragma unroll
        for (int j = 0; j < 4; j++) {
            int col = n0 + tx * 4 + j;
            Y[row * ND + col] = elu_f(acc[i][j] + bias[col]);
        }
    }
}

// =====================================================================
// Kernel 2 (monster, mma.sync fp16x3): persistent 128 blocks x 16 tiles.
// Per tile (b,h,q): D[128k,512f] = A @ W with A,W split hp16 hi/lo:
//   D = Ahi@Whi + Alo@Whi + Ahi@Wlo   (lo@lo dropped, ~2^-22)
// Epilogue fused in registers: y=relu(D+bKB); logits[k]=y@Wb; pool[f]=sum_k y*mk.
// 256 threads = 8 warps; warp w owns k rows [16w, 16w+16).
// smem rows are 128B with XOR-16B swizzle: chunk' = chunk ^ (row&7).
// =====================================================================
#define SW_WT_HI 0                    // half [512 f][64 d]  = 65536
#define SW_WT_LO 65536                // 65536
#define SW_A_HI  131072               // half [128 k][64 d]  = 16384
#define SW_A_LO  147456               // 16384
#define SW_EKK   163840               // float [128][65]     = 33280
#define SW_EQK   197120               // float [64]          = 256
#define SW_MASK  197376               // float [128]         = 512
#define SW_WB    197888               // float [512]         = 2048
#define SW_BKB   199936               // float [512]         = 2048
#define SW_POOLW 201984               // float [8][128]      = 4096
#define SMEM_MMA 206080

__global__ __launch_bounds__(256, 1) void k_bk_mma(
    const float* __restrict__ WKB, const float* __restrict__ bKB,
    const float* __restrict__ Wb,  const float* __restrict__ mask)
{
    extern __shared__ char smem[];
    uint32_t sb = smem_to_u32(smem);
    float* sEkk  = (float*)(smem + SW_EKK);
    float* sEqk  = (float*)(smem + SW_EQK);
    float* sMask = (float*)(smem + SW_MASK);
    float* sWb   = (float*)(smem + SW_WB);
    float* sBKB  = (float*)(smem + SW_BKB);
    float* sPoolW = (float*)(smem + SW_POOLW);

    int tid = threadIdx.x;
    int w = tid >> 5, lane = tid & 31;
    int g = lane >> 2, tig = lane & 3;
    int t0 = blockIdx.x * 16;
    int b = t0 >> 10, h = (t0 >> 7) & 7;
    int hd0 = h * NKD;

    // ---- stage W hi/lo into swizzled smem (once per block) ----
    for (int i = tid; i < NFB * 32; i += 256) {
        int f = i & 511;
        int dp = (i >> 9) * 2;                     // even d
        float w0 = WKB[dp * NFB + f];
        float w1 = WKB[(dp + 1) * NFB + f];
        __half h0 = __float2half_rn(w0);
        __half h1 = __float2half_rn(w1);
        __half l0 = __float2half_rn(w0 - __half2float(h0));
        __half l1 = __float2half_rn(w1 - __half2float(h1));
        uint32_t off = (uint32_t)(f * 128 + (((dp >> 3) ^ (f & 7)) << 4) + (dp & 7) * 2);
        *(__half2*)(smem + SW_WT_HI + off) = __halves2half2(h0, h1);
        *(__half2*)(smem + SW_WT_LO + off) = __halves2half2(l0, l1);
    }
    // ---- ekk (constant per block) ----
    const float* ekk_base = g_ekk + (size_t)(b * NS) * ND + hd0;
    for (int i = tid; i < NS * NKD; i += 256) {
        int k = i >> 6, d = i & 63;
        sEkk[k * 65 + d] = ekk_base[(size_t)k * ND + d];
    }
    for (int i = tid; i < NFB; i += 256) { sWb[i] = Wb[i]; sBKB[i] = bKB[i]; }
    __syncthreads();

    int arow = w * 16 + (lane & 7) + (lane & 8);
    int dhalf = lane >> 4;

    for (int it = 0; it < 16; it++) {
        int t = t0 + it;
        int qq = t & 127;
        int rowq = b * NS + qq;

        if (tid < 64) sEqk[tid] = g_eqk[(size_t)rowq * ND + hd0 + tid];
        else if (tid >= 128) sMask[tid - 128] = mask[(size_t)rowq * NS + tid - 128];
        __syncthreads();

        // ---- build A hi/lo: thread handles (k = tid>>1, 32 d) ----
        {
            int k = tid >> 1;
            int dh = (tid & 1) * 32;
            const float* eq = sEqk + dh;
            const float* er = sEkk + k * 65 + dh;
            uint32_t rowoff = (uint32_t)(k * 128);
            int klow = k & 7;
            #pragma unroll
            for (int j = 0; j < 16; j++) {
                int d = dh + 2 * j;
                float a0 = eq[2 * j] * er[2 * j];
                float a1 = eq[2 * j + 1] * er[2 * j + 1];
                __half h0 = __float2half_rn(a0);
                __half h1 = __float2half_rn(a1);
                __half l0 = __float2half_rn(a0 - __half2float(h0));
                __half l1 = __float2half_rn(a1 - __half2float(h1));
                uint32_t off = rowoff + (uint32_t)((((d >> 3) ^ klow) << 4) + (d & 7) * 2);
                *(__half2*)(smem + SW_A_HI + off) = __halves2half2(h0, h1);
                *(__half2*)(smem + SW_A_LO + off) = __halves2half2(l0, l1);
            }
        }
        __syncthreads();

        float llog0 = 0.f, llog1 = 0.f;
        int kr0 = w * 16 + g, kr1 = kr0 + 8;
        float mk0 = sMask[kr0], mk1 = sMask[kr1];

        #pragma unroll 1
        for (int cf = 0; cf < 4; cf++) {
            float acc[16][4];
            #pragma unroll
            for (int nt = 0; nt < 16; nt++)
                #pragma unroll
                for (int c = 0; c < 4; c++) acc[nt][c] = 0.f;

            #pragma unroll
            for (int ks = 0; ks < 4; ks++) {
                int chnk = ks * 2 + dhalf;
                uint32_t aoff = (uint32_t)(arow * 128 + ((chnk ^ (arow & 7)) << 4));
                uint32_t ah0, ah1, ah2, ah3, al0, al1, al2, al3;
                LDSM4(ah0, ah1, ah2, ah3, sb + SW_A_HI + aoff);
                LDSM4(al0, al1, al2, al3, sb + SW_A_LO + aoff);
                #pragma unroll
                for (int ntp = 0; ntp < 8; ntp++) {
                    int frow = cf * 128 + ntp * 16 + (lane & 7) + (lane & 8);
                    uint32_t boff = (uint32_t)(frow * 128 + ((chnk ^ (frow & 7)) << 4));
                    uint32_t bh0, bh1, bh2, bh3, bl0, bl1, bl2, bl3;
                    LDSM4(bh0, bh1, bh2, bh3, sb + SW_WT_HI + boff);
                    LDSM4(bl0, bl1, bl2, bl3, sb + SW_WT_LO + boff);
                    MMA16816(acc[2 * ntp],     ah0, ah1, ah2, ah3, bh0, bh2);
                    MMA16816(acc[2 * ntp + 1], ah0, ah1, ah2, ah3, bh1, bh3);
                    MMA16816(acc[2 * ntp],     al0, al1, al2, al3, bh0, bh2);
                    MMA16816(acc[2 * ntp + 1], al0, al1, al2, al3, bh1, bh3);
                    MMA16816(acc[2 * ntp],     ah0, ah1, ah2, ah3, bl0, bl2);
                    MMA16816(acc[2 * ntp + 1], ah0, ah1, ah2, ah3, bl1, bl3);
                }
            }

            // ---- chunk epilogue ----
            int fb = cf * 128;
            #pragma unroll
            for (int nt = 0; nt < 16; nt++) {
                int f = fb + nt * 8 + 2 * tig;
                float bk0 = sBKB[f], bk1 = sBKB[f + 1];
                float y00 = fmaxf(acc[nt][0] + bk0, 0.f);
                float y01 = fmaxf(acc[nt][1] + bk1, 0.f);
                float y10 = fmaxf(acc[nt][2] + bk0, 0.f);
                float y11 = fmaxf(acc[nt][3] + bk1, 0.f);
                llog0 += y00 * sWb[f] + y01 * sWb[f + 1];
                llog1 += y10 * sWb[f] + y11 * sWb[f + 1];
                float p0 = y00 * mk0 + y10 * mk1;
                float p1 = y01 * mk0 + y11 * mk1;
                p0 += __shfl_xor_sync(0xffffffffu, p0, 4);
                p0 += __shfl_xor_sync(0xffffffffu, p0, 8);
                p0 += __shfl_xor_sync(0xffffffffu, p0, 16);
                p1 += __shfl_xor_sync(0xffffffffu, p1, 4);
                p1 += __shfl_xor_sync(0xffffffffu, p1, 8);
                p1 += __shfl_xor_sync(0xffffffffu, p1, 16);
                if (lane < 4) {
                    sPoolW[w * 128 + nt * 8 + 2 * lane]     = p0;
                    sPoolW[w * 128 + nt * 8 + 2 * lane + 1] = p1;
                }
            }
            __syncthreads();
            if (tid < 128) {
                float s = 0.f;
                #pragma unroll
                for (int ww = 0; ww < 8; ww++) s += sPoolW[ww * 128 + tid];
                g_pool[(size_t)t * NFB + fb + tid] = s;
            }
            __syncthreads();
        }

        // ---- logits: reduce over tig quad ----
        llog0 += __shfl_xor_sync(0xffffffffu, llog0, 1);
        llog0 += __shfl_xor_sync(0xffffffffu, llog0, 2);
        llog1 += __shfl_xor_sync(0xffffffffu, llog1, 1);
        llog1 += __shfl_xor_sync(0xffffffffu, llog1, 2);
        if (tig == 0) {
            g_logits[(size_t)t * NS + kr0] = llog0;
            g_logits[(size_t)t * NS + kr1] = llog1;
        }
        __syncthreads();   // all done with sEqk/sMask/A before next tile rewrites
    }
}

// =====================================================================
// Kernel 3: softmax + pool-avg -> channel sigmoid + ctx
// =====================================================================
__global__ __launch_bounds__(128) void k_epi(
    const float* __restrict__ mask, const float* __restrict__ bbp,
    const float* __restrict__ We,   const float* __restrict__ be)
{
    __shared__ float sred[128];
    __shared__ float sattn[128];
    __shared__ float spav[512];
    __shared__ float sc1[128];
    __shared__ float sc2[128];

    int tid = threadIdx.x;
    int bhq = blockIdx.x;
    int b = bhq >> 10, h = (bhq >> 7) & 7, qq = bhq & 127;
    int hd0 = h * NKD;
    int rowq = b * NS + qq;

    float mk = mask[(size_t)rowq * NS + tid];
    float lg = g_logits[(size_t)bhq * NS + tid] + bbp[0] + (1.f - mk) * (-1e9f);

    sred[tid] = lg; __syncthreads();
    for (int s = 64; s > 0; s >>= 1) {
        if (tid < s) sred[tid] = fmaxf(sred[tid], sred[tid + s]);
        __syncthreads();
    }
    float m = sred[0]; __syncthreads();
    float e = expf(lg - m);
    sred[tid] = e; __syncthreads();
    for (int s = 64; s > 0; s >>= 1) {
        if (tid < s) sred[tid] += sred[tid + s];
        __syncthreads();
    }
    float esum = sred[0]; __syncthreads();
    sattn[tid] = e / esum;
    sred[tid] = mk; __syncthreads();
    for (int s = 64; s > 0; s >>= 1) {
        if (tid < s) sred[tid] += sred[tid + s];
        __syncthreads();
    }
    float msum = sred[0]; __syncthreads();

    for (int f = tid; f < NFB; f += 128)
        spav[f] = g_pool[(size_t)bhq * NFB + f] / msum;
    __syncthreads();

    int d = tid & 63, hf = tid >> 6;
    {
        float a0 = 0, a1 = 0, a2 = 0, a3 = 0;
        const float* Wep = We + d;
        int fb = hf * 256;
        #pragma unroll 4
        for (int f = fb; f < fb + 256; f += 4) {
            a0 = fmaf(spav[f],     Wep[(size_t)f * NKD],       a0);
            a1 = fmaf(spav[f + 1], Wep[(size_t)(f + 1) * NKD], a1);
            a2 = fmaf(spav[f + 2], Wep[(size_t)(f + 2) * NKD], a2);
            a3 = fmaf(spav[f + 3], Wep[(size_t)(f + 3) * NKD], a3);
        }
        sc1[tid] = (a0 + a1) + (a2 + a3);
    }
    {
        float c0 = 0, c1 = 0, c2 = 0, c3 = 0;
        const float* evvp = g_evv + (size_t)(b * NS) * ND + hd0 + d;
        int kb = hf * 64;
        #pragma unroll 4
        for (int k = kb; k < kb + 64; k += 4) {
            c0 = fmaf(sattn[k],     evvp[(size_t)k * ND],       c0);
            c1 = fmaf(sattn[k + 1], evvp[(size_t)(k + 1) * ND], c1);
            c2 = fmaf(sattn[k + 2], evvp[(size_t)(k + 2) * ND], c2);
            c3 = fmaf(sattn[k + 3], evvp[(size_t)(k + 3) * ND], c3);
        }
        sc2[tid] = (c0 + c1) + (c2 + c3);
    }
    __syncthreads();
    if (tid < 64) {
        float ch = 1.f / (1.f + expf(-(sc1[tid] + sc1[tid + 64] + be[tid])));
        float cs = sc2[tid] + sc2[tid + 64];
        g_O[(size_t)rowq * ND + hd0 + tid] =
            g_eqv[(size_t)rowq * ND + hd0 + tid] * cs * ch;
    }
}

// =====================================================================
// Kernel 4: out = O @ Wd + bd  (256x512)@(512x64)
// =====================================================================
__global__ __launch_bounds__(128) void k_final(
    const float* __restrict__ Wd, const float* __restrict__ bd,
    float* __restrict__ out)
{
    __shared__ float sc[128];
    int tid = threadIdx.x;
    int r = blockIdx.x;
    int c = tid & 63, hf = tid >> 6;
    const float* orow = g_O + (size_t)r * ND + hf * 256;
    const float* wp = Wd + (size_t)(hf * 256) * NKD + c;
    float a0 = 0, a1 = 0, a2 = 0, a3 = 0;
    #pragma unroll 8
    for (int dd = 0; dd < 256; dd += 4) {
        a0 = fmaf(orow[dd],     wp[(size_t)dd * NKD],       a0);
        a1 = fmaf(orow[dd + 1], wp[(size_t)(dd + 1) * NKD], a1);
        a2 = fmaf(orow[dd + 2], wp[(size_t)(dd + 2) * NKD], a2);
        a3 = fmaf(orow[dd + 3], wp[(size_t)(dd + 3) * NKD], a3);
    }
    sc[tid] = (a0 + a1) + (a2 + a3);
    __syncthreads();
    if (tid < 64)
        out[(size_t)r * NKD + tid] = sc[tid] + sc[tid + 64] + bd[tid];
}

// =====================================================================
extern "C" void kernel_launch(void* const* d_in, const int* in_sizes, int n_in,
                              void* d_out, int out_size)
{
    const float* q    = (const float*)d_in[0];
    const float* v    = (const float*)d_in[1];
    const float* mask = (const float*)d_in[2];
    const float* Wkq  = (const float*)d_in[3];
    const float* bkq  = (const float*)d_in[4];
    const float* Wvq  = (const float*)d_in[5];
    const float* bvq  = (const float*)d_in[6];
    const float* Wk   = (const float*)d_in[7];
    const float* bk   = (const float*)d_in[8];
    const float* Wv   = (const float*)d_in[9];
    const float* bv   = (const float*)d_in[10];
    const float* WKB  = (const float*)d_in[11];
    const float* bKB  = (const float*)d_in[12];
    const float* Wb   = (const float*)d_in[13];
    const float* bb   = (const float*)d_in[14];
    const float* We   = (const float*)d_in[15];
    const float* be   = (const float*)d_in[16];
    const float* Wd   = (const float*)d_in[17];
    const float* bd   = (const float*)d_in[18];
    float* out = (float*)d_out;

    cudaFuncSetAttribute(k_bk_mma, cudaFuncAttributeMaxDynamicSharedMemorySize, SMEM_MMA);

    k_proj<<<dim3(8, 4, 4), 256>>>(q, v, Wkq, bkq, Wvq, bvq, Wk, bk, Wv, bv);
    k_bk_mma<<<128, 256, SMEM_MMA>>>(WKB, bKB, Wb, mask);
    k_epi<<<NBHQ, 128>>>(mask, bb, We, be);
    k_final<<<256, 128>>>(Wd, bd, out);
}